// round 4
// baseline (speedup 1.0000x reference)
#include <cuda_runtime.h>
#include <stdint.h>

// Fixed shape family: B=1, H=8, D=64. N, E read from in_sizes at launch.
#define H 8
#define D 64

// Scratch (allocation-free): N*H entries needed (800k typical). 4M headroom.
static __device__ float        g_attn[1 << 22];  // tanh(attn[n,h])
static __device__ unsigned int g_m   [1 << 22];  // transformed-uint running max per (target,h)

// Monotone float->uint transform (order-preserving under unsigned compare).
__device__ __forceinline__ unsigned int f2key(unsigned int u) {
    return (u & 0x80000000u) ? ~u : (u | 0x80000000u);
}
__device__ __forceinline__ float key2f(unsigned int k) {
    unsigned int u = (k & 0x80000000u) ? (k ^ 0x80000000u) : ~k;
    return __uint_as_float(u);
}

// Fast tanh via hardware exp (MUFU.EX2): rel err ~1e-7, far inside tolerance.
__device__ __forceinline__ float fast_tanh(float x) {
    float e = __expf(2.0f * x);
    return 1.0f - __fdividef(2.0f, e + 1.0f);
}

// ── K1 (unchanged from R3, 39.7us @ 66.8% DRAM): warp per 2 adjacent rows,
// 8 independent LDG.128/lane in flight, W in 16 regs, streaming X loads.
__global__ void k1_attn(const float4* __restrict__ X4, const float* __restrict__ Wk,
                        int N, int totalWarps) {
    int wid  = (blockIdx.x * blockDim.x + threadIdx.x) >> 5;
    int lane = threadIdx.x & 31;
    int lo = lane & 15, hi = lane >> 4;

    float w[4][4];
    #pragma unroll
    for (int k = 0; k < 4; k++)
        #pragma unroll
        for (int j = 0; j < 4; j++)
            w[k][j] = Wk[(4 * lo + j) * H + 2 * k + hi];

    for (int n = wid * 2; n < N; n += totalWarps * 2) {
        const float4* r0 = X4 + (size_t)n * (H * D / 4);
        bool two = (n + 1 < N);
        float4 v0[4], v1[4];
        #pragma unroll
        for (int k = 0; k < 4; k++) v0[k] = __ldcs(r0 + lane + 32 * k);
        if (two) {
            #pragma unroll
            for (int k = 0; k < 4; k++) v1[k] = __ldcs(r0 + 128 + lane + 32 * k);
        }
        float s0[4], s1[4];
        #pragma unroll
        for (int k = 0; k < 4; k++) {
            s0[k] = v0[k].x * w[k][0] + v0[k].y * w[k][1] + v0[k].z * w[k][2] + v0[k].w * w[k][3];
            s1[k] = two ? (v1[k].x * w[k][0] + v1[k].y * w[k][1] + v1[k].z * w[k][2] + v1[k].w * w[k][3]) : 0.0f;
        }
        #pragma unroll
        for (int o = 8; o >= 1; o >>= 1) {
            #pragma unroll
            for (int k = 0; k < 4; k++) {
                s0[k] += __shfl_xor_sync(0xffffffffu, s0[k], o);
                s1[k] += __shfl_xor_sync(0xffffffffu, s1[k], o);
            }
        }
        if (lo == 0) {
            float* ar = g_attn + (size_t)n * H;
            #pragma unroll
            for (int k = 0; k < 4; k++) ar[2 * k + hi] = fast_tanh(s0[k]);
            if (two) {
                #pragma unroll
                for (int k = 0; k < 4; k++) ar[H + 2 * k + hi] = fast_tanh(s1[k]);
            }
            if (hi == 0) {                     // re-init m keys every call
                uint4 z = make_uint4(0u, 0u, 0u, 0u);
                uint4* mz = (uint4*)(g_m + (size_t)n * H);
                mz[0] = z; mz[1] = z;
                if (two) { mz[2] = z; mz[3] = z; }
            }
        }
    }
}

// ── K2: one thread per (edge, h). 4B gathers (<=8 sectors/warp instead of
// 32-sector LDG.128 replays), 8 lanes share each src/tgt sector, huge thread
// pool hides L2 latency. Racy read-filter before atomicMax (stale-low reads
// only cost an extra atomic, never correctness).
__global__ void k2_max(const int* __restrict__ src, const int* __restrict__ tgt, int EH) {
    int i = blockIdx.x * blockDim.x + threadIdx.x;
    if (i >= EH) return;
    int e = i >> 3, h = i & 7;
    int s = __ldg(src + e), t = __ldg(tgt + e);
    unsigned int a   = ((const unsigned int*)g_attn)[(size_t)s * H + h];
    unsigned int key = f2key(a);
    unsigned int* mp = g_m + (size_t)t * H + h;
    if (key > *mp) atomicMax(mp, key);
}

// ── K3: one thread per (edge, h). out[e,h] = exp(attn[src,h]-m[tgt,h])*drop[e,h].
// (Denominator segment_max(exp(e-m)) + 1e-9 == 1.0f exactly in fp32: every
// segment attains exp(0)=1 and 1e-9 underflows the ulp of 1.0.)
// drop/out fully coalesced 128B per warp; gathers are 4B single-sector.
__global__ void k3_out(const int* __restrict__ src, const int* __restrict__ tgt,
                       const float* __restrict__ drop, float* __restrict__ out, int EH) {
    int i = blockIdx.x * blockDim.x + threadIdx.x;
    if (i >= EH) return;
    int e = i >> 3, h = i & 7;
    int s = __ldg(src + e), t = __ldg(tgt + e);
    float a = g_attn[(size_t)s * H + h];
    float m = key2f(g_m[(size_t)t * H + h]);
    out[i] = __expf(a - m) * drop[i];
}

// Inputs (metadata order): 0:X(f32) 1:attn_kernel(f32 D*H) 2:targets(i32 E)
// 3:sources(i32 E) 4:degree(f32 N, unused) 5:drop_mask(f32 E*H) 6:N.
extern "C" void kernel_launch(void* const* d_in, const int* in_sizes, int n_in,
                              void* d_out, int out_size) {
    const float4* X4   = (const float4*)d_in[0];
    const float*  Wk   = (const float*)d_in[1];
    const int*    tgt  = (const int*)d_in[2];
    const int*    srcs = (const int*)d_in[3];
    const float*  drop = (const float*)d_in[5];
    float*        out  = (float*)d_out;

    const int E = in_sizes[2];
    const int N = in_sizes[4];

    const int k1_blocks = 1184;
    k1_attn<<<k1_blocks, 256>>>(X4, Wk, N, k1_blocks * (256 / 32));

    const int EH = E * H;
    const int block = 256;
    const int grid  = (EH + block - 1) / block;
    k2_max<<<grid, block>>>(srcs, tgt, EH);
    k3_out<<<grid, block>>>(srcs, tgt, drop, out, EH);
}

// round 5
// speedup vs baseline: 1.5763x; 1.5763x over previous
#include <cuda_runtime.h>
#include <stdint.h>

// Fixed shape family: B=1, H=8, D=64. N, E read from in_sizes at launch.
#define H 8
#define D 64

// Scratch (allocation-free): N*H entries needed (800k typical). 4M headroom.
static __device__ float        g_attn[1 << 22];  // tanh(attn[n,h])
static __device__ unsigned int g_m   [1 << 22];  // transformed-uint running max per (target,h)

// Monotone float->uint transform (order-preserving under unsigned compare).
__device__ __forceinline__ unsigned int f2key(unsigned int u) {
    return (u & 0x80000000u) ? ~u : (u | 0x80000000u);
}
__device__ __forceinline__ float key2f(unsigned int k) {
    unsigned int u = (k & 0x80000000u) ? (k ^ 0x80000000u) : ~k;
    return __uint_as_float(u);
}

// Fast tanh via hardware exp (MUFU.EX2): rel err ~1e-7, far inside tolerance.
__device__ __forceinline__ float fast_tanh(float x) {
    float e = __expf(2.0f * x);
    return 1.0f - __fdividef(2.0f, e + 1.0f);
}

// ── K1: warp per 2 adjacent rows, 8 independent LDG.128/lane in flight,
// W in 16 regs, streaming X loads. launch_bounds caps regs at 48 -> 5
// blocks/SM (40 warps) vs 4 at 56 regs: more loads in flight per SM.
__global__ void __launch_bounds__(256, 5)
k1_attn(const float4* __restrict__ X4, const float* __restrict__ Wk,
        int N, int totalWarps) {
    int wid  = (blockIdx.x * blockDim.x + threadIdx.x) >> 5;
    int lane = threadIdx.x & 31;
    int lo = lane & 15, hi = lane >> 4;

    float w[4][4];
    #pragma unroll
    for (int k = 0; k < 4; k++)
        #pragma unroll
        for (int j = 0; j < 4; j++)
            w[k][j] = Wk[(4 * lo + j) * H + 2 * k + hi];

    for (int n = wid * 2; n < N; n += totalWarps * 2) {
        const float4* r0 = X4 + (size_t)n * (H * D / 4);
        bool two = (n + 1 < N);
        float4 v0[4], v1[4];
        #pragma unroll
        for (int k = 0; k < 4; k++) v0[k] = __ldcs(r0 + lane + 32 * k);
        if (two) {
            #pragma unroll
            for (int k = 0; k < 4; k++) v1[k] = __ldcs(r0 + 128 + lane + 32 * k);
        }
        float s0[4], s1[4];
        #pragma unroll
        for (int k = 0; k < 4; k++) {
            s0[k] = v0[k].x * w[k][0] + v0[k].y * w[k][1] + v0[k].z * w[k][2] + v0[k].w * w[k][3];
            s1[k] = two ? (v1[k].x * w[k][0] + v1[k].y * w[k][1] + v1[k].z * w[k][2] + v1[k].w * w[k][3]) : 0.0f;
        }
        #pragma unroll
        for (int o = 8; o >= 1; o >>= 1) {
            #pragma unroll
            for (int k = 0; k < 4; k++) {
                s0[k] += __shfl_xor_sync(0xffffffffu, s0[k], o);
                s1[k] += __shfl_xor_sync(0xffffffffu, s1[k], o);
            }
        }
        if (lo == 0) {
            float* ar = g_attn + (size_t)n * H;
            #pragma unroll
            for (int k = 0; k < 4; k++) ar[2 * k + hi] = fast_tanh(s0[k]);
            if (two) {
                #pragma unroll
                for (int k = 0; k < 4; k++) ar[H + 2 * k + hi] = fast_tanh(s1[k]);
            }
            if (hi == 0) {                     // re-init m keys every call
                uint4 z = make_uint4(0u, 0u, 0u, 0u);
                uint4* mz = (uint4*)(g_m + (size_t)n * H);
                mz[0] = z; mz[1] = z;
                if (two) { mz[2] = z; mz[3] = z; }
            }
        }
    }
}

// ── K2 (R2 verbatim — empirically best): thread per edge, uint4 gathers
// (4x fewer L2 requests than scalar), racy read-filter before atomicMax
// (stale-low reads only cost an extra atomic, never correctness).
__global__ void k2_max(const int* __restrict__ src, const int* __restrict__ tgt, int E) {
    int i = blockIdx.x * blockDim.x + threadIdx.x;
    if (i >= E) return;
    int s = src[i], t = tgt[i];
    const uint4* av = (const uint4*)(g_attn + (size_t)s * H);
    uint4 a0 = av[0], a1 = av[1];
    unsigned int key[H] = { f2key(a0.x), f2key(a0.y), f2key(a0.z), f2key(a0.w),
                            f2key(a1.x), f2key(a1.y), f2key(a1.z), f2key(a1.w) };
    unsigned int* mv = g_m + (size_t)t * H;
    const uint4* mvv = (const uint4*)mv;
    uint4 m0 = mvv[0], m1 = mvv[1];
    unsigned int cur[H] = { m0.x, m0.y, m0.z, m0.w, m1.x, m1.y, m1.z, m1.w };
    #pragma unroll
    for (int h = 0; h < H; h++)
        if (key[h] > cur[h]) atomicMax(&mv[h], key[h]);
}

// ── K3 (R2 verbatim): thread per edge, out[i,h]=exp(attn[src,h]-m[tgt,h])*drop.
// (Denominator segment_max(exp(e-m)) + 1e-9 == 1.0f exactly in fp32: every
// segment attains exp(0)=1 and 1e-9 underflows the ulp of 1.0.)
__global__ void k3_out(const int* __restrict__ src, const int* __restrict__ tgt,
                       const float4* __restrict__ drop4, float4* __restrict__ out4, int E) {
    int i = blockIdx.x * blockDim.x + threadIdx.x;
    if (i >= E) return;
    int s = src[i], t = tgt[i];
    const float4* av = (const float4*)(g_attn + (size_t)s * H);
    float4 a0 = av[0], a1 = av[1];
    const uint4* mv = (const uint4*)(g_m + (size_t)t * H);
    uint4 m0 = mv[0], m1 = mv[1];
    float4 d0 = drop4[(size_t)i * 2], d1 = drop4[(size_t)i * 2 + 1];
    float4 o0, o1;
    o0.x = __expf(a0.x - key2f(m0.x)) * d0.x;
    o0.y = __expf(a0.y - key2f(m0.y)) * d0.y;
    o0.z = __expf(a0.z - key2f(m0.z)) * d0.z;
    o0.w = __expf(a0.w - key2f(m0.w)) * d0.w;
    o1.x = __expf(a1.x - key2f(m1.x)) * d1.x;
    o1.y = __expf(a1.y - key2f(m1.y)) * d1.y;
    o1.z = __expf(a1.z - key2f(m1.z)) * d1.z;
    o1.w = __expf(a1.w - key2f(m1.w)) * d1.w;
    out4[(size_t)i * 2]     = o0;
    out4[(size_t)i * 2 + 1] = o1;
}

// Inputs (metadata order): 0:X(f32) 1:attn_kernel(f32 D*H) 2:targets(i32 E)
// 3:sources(i32 E) 4:degree(f32 N, unused) 5:drop_mask(f32 E*H) 6:N.
extern "C" void kernel_launch(void* const* d_in, const int* in_sizes, int n_in,
                              void* d_out, int out_size) {
    const float4* X4   = (const float4*)d_in[0];
    const float*  Wk   = (const float*)d_in[1];
    const int*    tgt  = (const int*)d_in[2];
    const int*    srcs = (const int*)d_in[3];
    const float4* drop = (const float4*)d_in[5];
    float4*       out  = (float4*)d_out;

    const int E = in_sizes[2];
    const int N = in_sizes[4];

    const int k1_blocks = 1184;
    k1_attn<<<k1_blocks, 256>>>(X4, Wk, N, k1_blocks * (256 / 32));

    const int block = 256;
    const int grid  = (E + block - 1) / block;
    k2_max<<<grid, block>>>(srcs, tgt, E);
    k3_out<<<grid, block>>>(srcs, tgt, drop, out, E);
}

// round 6
// speedup vs baseline: 1.8753x; 1.1897x over previous
#include <cuda_runtime.h>
#include <stdint.h>

// Fixed shape family: B=1, H=8, D=64. N, E read from in_sizes at launch.
#define H 8
#define D 64

// Scratch (allocation-free): N*H entries needed (800k typical). 4M headroom.
static __device__ float        g_attn[1 << 22];  // tanh(attn[n,h])
static __device__ unsigned int g_m   [1 << 22];  // transformed-uint running max per (target,h)

// Monotone float->uint transform (order-preserving under unsigned compare).
__device__ __forceinline__ unsigned int f2key(unsigned int u) {
    return (u & 0x80000000u) ? ~u : (u | 0x80000000u);
}
__device__ __forceinline__ float key2f(unsigned int k) {
    unsigned int u = (k & 0x80000000u) ? (k ^ 0x80000000u) : ~k;
    return __uint_as_float(u);
}

// Fast tanh via hardware exp (MUFU.EX2): rel err ~1e-7, far inside tolerance.
__device__ __forceinline__ float fast_tanh(float x) {
    float e = __expf(2.0f * x);
    return 1.0f - __fdividef(2.0f, e + 1.0f);
}

// ── K1 (R3 exact, known 39.7us @ 66.8% DRAM; no launch_bounds — the 48-reg
// cap experiment regressed it): warp per 2 adjacent rows, 8 independent
// LDG.128/lane in flight, W in 16 regs, streaming X loads.
__global__ void k1_attn(const float4* __restrict__ X4, const float* __restrict__ Wk,
                        int N, int totalWarps) {
    int wid  = (blockIdx.x * blockDim.x + threadIdx.x) >> 5;
    int lane = threadIdx.x & 31;
    int lo = lane & 15, hi = lane >> 4;

    float w[4][4];
    #pragma unroll
    for (int k = 0; k < 4; k++)
        #pragma unroll
        for (int j = 0; j < 4; j++)
            w[k][j] = Wk[(4 * lo + j) * H + 2 * k + hi];

    for (int n = wid * 2; n < N; n += totalWarps * 2) {
        const float4* r0 = X4 + (size_t)n * (H * D / 4);
        bool two = (n + 1 < N);
        float4 v0[4], v1[4];
        #pragma unroll
        for (int k = 0; k < 4; k++) v0[k] = __ldcs(r0 + lane + 32 * k);
        if (two) {
            #pragma unroll
            for (int k = 0; k < 4; k++) v1[k] = __ldcs(r0 + 128 + lane + 32 * k);
        }
        float s0[4], s1[4];
        #pragma unroll
        for (int k = 0; k < 4; k++) {
            s0[k] = v0[k].x * w[k][0] + v0[k].y * w[k][1] + v0[k].z * w[k][2] + v0[k].w * w[k][3];
            s1[k] = two ? (v1[k].x * w[k][0] + v1[k].y * w[k][1] + v1[k].z * w[k][2] + v1[k].w * w[k][3]) : 0.0f;
        }
        #pragma unroll
        for (int o = 8; o >= 1; o >>= 1) {
            #pragma unroll
            for (int k = 0; k < 4; k++) {
                s0[k] += __shfl_xor_sync(0xffffffffu, s0[k], o);
                s1[k] += __shfl_xor_sync(0xffffffffu, s1[k], o);
            }
        }
        if (lo == 0) {
            float* ar = g_attn + (size_t)n * H;
            #pragma unroll
            for (int k = 0; k < 4; k++) ar[2 * k + hi] = fast_tanh(s0[k]);
            if (two) {
                #pragma unroll
                for (int k = 0; k < 4; k++) ar[H + 2 * k + hi] = fast_tanh(s1[k]);
            }
            if (hi == 0) {                     // re-init m keys every call
                uint4 z = make_uint4(0u, 0u, 0u, 0u);
                uint4* mz = (uint4*)(g_m + (size_t)n * H);
                mz[0] = z; mz[1] = z;
                if (two) { mz[2] = z; mz[3] = z; }
            }
        }
    }
}

// ── K2: 2 lanes per edge. Each lane LDG.128s HALF the attn row and half the
// m row -> one gather instruction touches 16 distinct lines for 16 edges
// (1 L1 wavefront per edge per table vs 2 before). Pair-shared index loads
// broadcast. Racy read-filter before atomicMax (stale-low reads only cost an
// extra atomic, never correctness).
__global__ void k2_max(const int* __restrict__ src, const int* __restrict__ tgt, int E) {
    int idx  = blockIdx.x * blockDim.x + threadIdx.x;
    int e    = idx >> 1;
    int half = idx & 1;
    if (e >= E) return;
    int s = __ldg(src + e), t = __ldg(tgt + e);
    uint4 a = *(const uint4*)(g_attn + (size_t)s * H + half * 4);
    unsigned int* mp = g_m + (size_t)t * H + half * 4;
    uint4 cur = *(const uint4*)mp;
    unsigned int k0 = f2key(a.x), k1 = f2key(a.y), k2 = f2key(a.z), k3 = f2key(a.w);
    if (k0 > cur.x) atomicMax(mp + 0, k0);
    if (k1 > cur.y) atomicMax(mp + 1, k1);
    if (k2 > cur.z) atomicMax(mp + 2, k2);
    if (k3 > cur.w) atomicMax(mp + 3, k3);
}

// ── K3: 2 lanes per edge, same half-row gather trick. drop read and out
// write are 512B contiguous per warp per instruction (perfectly coalesced).
// out[e,h] = exp(attn[src,h] - m[tgt,h]) * drop[e,h]. (Denominator
// segment_max(exp(e-m)) + 1e-9 == 1.0f exactly in fp32: every segment
// attains exp(0)=1 and 1e-9 underflows the ulp of 1.0.)
__global__ void k3_out(const int* __restrict__ src, const int* __restrict__ tgt,
                       const float4* __restrict__ drop4, float4* __restrict__ out4, int E) {
    int idx  = blockIdx.x * blockDim.x + threadIdx.x;
    int e    = idx >> 1;
    int half = idx & 1;
    if (e >= E) return;
    int s = __ldg(src + e), t = __ldg(tgt + e);
    float4 a = *(const float4*)(g_attn + (size_t)s * H + half * 4);
    uint4  m = *(const uint4*) (g_m    + (size_t)t * H + half * 4);
    float4 d = drop4[(size_t)e * 2 + half];
    float4 o;
    o.x = __expf(a.x - key2f(m.x)) * d.x;
    o.y = __expf(a.y - key2f(m.y)) * d.y;
    o.z = __expf(a.z - key2f(m.z)) * d.z;
    o.w = __expf(a.w - key2f(m.w)) * d.w;
    out4[(size_t)e * 2 + half] = o;
}

// Inputs (metadata order): 0:X(f32) 1:attn_kernel(f32 D*H) 2:targets(i32 E)
// 3:sources(i32 E) 4:degree(f32 N, unused) 5:drop_mask(f32 E*H) 6:N.
extern "C" void kernel_launch(void* const* d_in, const int* in_sizes, int n_in,
                              void* d_out, int out_size) {
    const float4* X4   = (const float4*)d_in[0];
    const float*  Wk   = (const float*)d_in[1];
    const int*    tgt  = (const int*)d_in[2];
    const int*    srcs = (const int*)d_in[3];
    const float4* drop = (const float4*)d_in[5];
    float4*       out  = (float4*)d_out;

    const int E = in_sizes[2];
    const int N = in_sizes[4];

    const int k1_blocks = 1184;
    k1_attn<<<k1_blocks, 256>>>(X4, Wk, N, k1_blocks * (256 / 32));

    const int threads = E * 2;            // 2 lanes per edge
    const int block = 256;
    const int grid  = (threads + block - 1) / block;
    k2_max<<<grid, block>>>(srcs, tgt, E);
    k3_out<<<grid, block>>>(srcs, tgt, drop, out, E);
}